// round 14
// baseline (speedup 1.0000x reference)
#include <cuda_runtime.h>
#include <cuda_fp16.h>
#include <cstdint>
#include <cstddef>

// ---------------------------------------------------------------------------
// MPNN layer, fp32.  B=50000, K=32, D=128, E=32.  ALL GEMMs fp16 HMMA.
//  edge kernel: 256 threads, OCCUPANCY 2 (two CTAs per SM overlap phases),
//  128-row tiles, K32 sub-chunks, SMEM 112.5 KB/CTA.
// ---------------------------------------------------------------------------

#define B_  50000
#define K_  32
#define D_  128
#define E_  32

__device__ float g_aself[(size_t)B_ * D_];
__device__ float g_mi[(size_t)B_ * D_];

// ======================= helpers ===========================================
__device__ __forceinline__ uint32_t smem_u32(const void* p) {
    uint32_t a;
    asm("{ .reg .u64 t; cvta.to.shared.u64 t, %1; cvt.u32.u64 %0, t; }"
        : "=r"(a) : "l"(p));
    return a;
}
__device__ __forceinline__ uint32_t swz(uint32_t b) { return b ^ ((b >> 3) & 0x70); }
__device__ __forceinline__ uint32_t swz64(uint32_t b) { return b ^ ((b >> 3) & 0x30); }
__device__ __forceinline__ uint32_t packh2(float a, float b) {
    uint32_t r;
    asm("cvt.rn.f16x2.f32 %0, %1, %2;" : "=r"(r) : "f"(b), "f"(a));
    return r;
}
__device__ __forceinline__ uint16_t packh1(float a) {
    uint16_t r;
    asm("cvt.rn.f16.f32 %0, %1;" : "=h"(r) : "f"(a));
    return r;
}
__device__ __forceinline__ void ldsm4(uint32_t* r, uint32_t addr) {
    asm volatile("ldmatrix.sync.aligned.m8n8.x4.shared.b16 {%0,%1,%2,%3}, [%4];"
                 : "=r"(r[0]), "=r"(r[1]), "=r"(r[2]), "=r"(r[3]) : "r"(addr));
}
__device__ __forceinline__ void mma16816(float* d, const uint32_t* a, const uint32_t* b) {
    asm("mma.sync.aligned.m16n8k16.row.col.f32.f16.f16.f32 "
        "{%0,%1,%2,%3}, {%4,%5,%6,%7}, {%8,%9}, {%0,%1,%2,%3};"
        : "+f"(d[0]), "+f"(d[1]), "+f"(d[2]), "+f"(d[3])
        : "r"(a[0]), "r"(a[1]), "r"(a[2]), "r"(a[3]), "r"(b[0]), "r"(b[1]));
}
#define CP_ASYNC16(dst, src) \
    asm volatile("cp.async.cg.shared.global [%0], [%1], 16;" :: "r"(dst), "l"(src))
#define CP_COMMIT() asm volatile("cp.async.commit_group;" ::: "memory")
#define CP_WAIT0()  asm volatile("cp.async.wait_group 0;" ::: "memory")

extern __shared__ float smem[];

// ---------------------------------------------------------------------------
// Kernel 1: a_self = h_self @ eW1[0:128,:] + eb1  (fp16 HMMA, cp.async pipe)
// ---------------------------------------------------------------------------
#define SW_OW 0        // weights 32768
#define SW_OST 32768   // fp32 staging 65536
#define SW_OA 98304    // A fp16 32768
#define SW_OEB 131072  // 512
#define SELF_SMEM 131584

__global__ __launch_bounds__(256, 1) void self_kernel(
    const float *__restrict__ h_self, const float *__restrict__ eW1,
    const float *__restrict__ eb1, int ntiles) {
    char *sm = (char *)smem;
    float *ebs = (float *)(sm + SW_OEB);
    const int tid = threadIdx.x;
    const int wid = tid >> 5, lane = tid & 31;
    const int wm = wid & 3, wn = wid >> 2;
    const int gid = lane >> 2, tig = lane & 3;
    const uint32_t sbase = smem_u32(sm);

    auto issue_dma = [&](int t2) {
        const int row0 = t2 * 128;
#pragma unroll
        for (int i = 0; i < 16; i++) {
            int q = tid + 256 * i;
            int row = q >> 5, c4 = (q & 31) * 4;
            int grow = row0 + row;
            if (grow > B_ - 1) grow = B_ - 1;
            CP_ASYNC16(sbase + SW_OST + q * 16, h_self + (size_t)grow * 128 + c4);
        }
        CP_COMMIT();
    };

    int tile = blockIdx.x;
    if (tile < ntiles) issue_dma(tile);

    for (int idx = tid; idx < 128 * 128; idx += 256) {
        int n = idx & 127, k = idx >> 7;
        int c = k >> 6, kk = k & 63;
        uint32_t off = c * 16384 + swz(n * 128 + kk * 2);
        *(uint16_t *)(sm + SW_OW + off) = packh1(eW1[(size_t)k * 128 + n]);
    }
    if (tid < 128) ebs[tid] = eb1[tid];

    const int arow = lane & 15;
    const int ak = (lane >> 4) * 8;
    const int brow = (lane & 7) + 8 * (lane >> 4);
    const int bk = 8 * ((lane >> 3) & 1);

    uint32_t AH[2][2][4], BH[2][4][4];
    auto ldA = [&](uint32_t baseA, int koff, uint32_t (&AHb)[2][4]) {
#pragma unroll
        for (int m = 0; m < 2; m++) {
            uint32_t off = swz((uint32_t)((32 * wm + 16 * m + arow) * 128 + koff * 2));
            ldsm4(AHb[m], baseA + off);
        }
    };
    auto ldB = [&](uint32_t baseB, int koff, uint32_t (&BHb)[4][4]) {
#pragma unroll
        for (int p = 0; p < 4; p++) {
            uint32_t off = swz((uint32_t)((64 * wn + 16 * p + brow) * 128 + koff * 2));
            ldsm4(BHb[p], baseB + off);
        }
    };

    for (; tile < ntiles; tile += gridDim.x) {
        const int row0 = tile * 128;
        __syncthreads();
        CP_WAIT0();
#pragma unroll
        for (int i = 0; i < 16; i++) {
            int q = tid + 256 * i;
            int r = q >> 5, c4 = (q & 31) * 4;
            float4 v = *(const float4 *)(sm + SW_OST + q * 16);
            uint32_t off = (c4 >> 6) * 16384 + swz((uint32_t)(r * 128 + (c4 & 63) * 2));
            *(uint2 *)(sm + SW_OA + off) =
                make_uint2(packh2(v.x, v.y), packh2(v.z, v.w));
        }
        __syncthreads();
        if (tile + gridDim.x < ntiles) issue_dma(tile + gridDim.x);

        float acc[2][8][4];
#pragma unroll
        for (int m = 0; m < 2; m++)
#pragma unroll
            for (int nt = 0; nt < 8; nt++)
#pragma unroll
                for (int j = 0; j < 4; j++) acc[m][nt][j] = 0.f;

        ldA(sbase + SW_OA, ak, AH[0]);
        ldB(sbase + SW_OW, bk, BH[0]);
#pragma unroll
        for (int ks = 0; ks < 8; ks++) {
            const int cur = ks & 1, nxt = cur ^ 1;
            if (ks + 1 < 8) {
                const int k2 = ks + 1, cb = k2 >> 2;
                ldA(sbase + SW_OA + cb * 16384, (k2 & 3) * 16 + ak, AH[nxt]);
                ldB(sbase + SW_OW + cb * 16384, (k2 & 3) * 16 + bk, BH[nxt]);
            }
#pragma unroll
            for (int m = 0; m < 2; m++)
#pragma unroll
                for (int p = 0; p < 4; p++) {
                    mma16816(acc[m][2 * p], AH[cur][m], &BH[cur][p][0]);
                    mma16816(acc[m][2 * p + 1], AH[cur][m], &BH[cur][p][2]);
                }
        }

#pragma unroll
        for (int nt = 0; nt < 8; nt++) {
            int c0 = 64 * wn + 8 * nt + 2 * tig;
            float bv0 = ebs[c0], bv1 = ebs[c0 + 1];
#pragma unroll
            for (int m = 0; m < 2; m++) {
                int r = 32 * wm + 16 * m + gid;
                int grow = row0 + r;
                if (grow < B_) {
                    float2 v = make_float2(acc[m][nt][0] + bv0, acc[m][nt][1] + bv1);
                    *(float2 *)(g_aself + (size_t)grow * 128 + c0) = v;
                }
                if (grow + 8 < B_) {
                    float2 v = make_float2(acc[m][nt][2] + bv0, acc[m][nt][3] + bv1);
                    *(float2 *)(g_aself + (size_t)(grow + 8) * 128 + c0) = v;
                }
            }
        }
    }
}

// ---------------------------------------------------------------------------
// Kernel 2: edge MLP. 256 threads, OCCUPANCY 2, 128-row tiles.
// SMEM (112.5 KB): B1 40 KB (2 SW128 blocks + 1 SW64 half-block),
//                  B2 32 KB, A 8 KB (SW64), Y 32 KB (2 SW128 blocks), mask.
// ---------------------------------------------------------------------------
#define OB1  0          // blocks 0,1: [n128][k64] SW128; +32768: [n128][k32] SW64
#define OB2  40960      // 2 x 16384 SW128
#define OA   73728      // 8192 SW64 [r128][k32]
#define OY   81920      // 2 x 16384 SW128 [r128][k64]
#define OMASK 114688    // 128 floats
#define EDGE_SMEM 115200

__global__ __launch_bounds__(256, 2) void edge_mma_kernel(
    const float *__restrict__ h_nei, const float *__restrict__ e_ij,
    const float *__restrict__ mask, const float *__restrict__ eW1,
    const float *__restrict__ eW2, const float *__restrict__ eb2, int ntiles) {
    char *sm = (char *)smem;
    float *mask_s = (float *)(sm + OMASK);
    const int tid = threadIdx.x;
    const int wid = tid >> 5, lane = tid & 31;
    const int wm = wid & 3, wn = wid >> 2;   // 4 M-groups x 2 N-groups
    const int gid = lane >> 2, tig = lane & 3;
    const uint32_t sbase = smem_u32(sm);

    // one-time: weights -> fp16 blocked
    for (int idx = tid; idx < 160 * 128; idx += 256) {
        int n = idx & 127, k = idx >> 7;
        uint32_t off;
        if (k < 128)
            off = (k >> 6) * 16384 + swz(n * 128 + (k & 63) * 2);
        else
            off = 32768 + swz64(n * 64 + (k - 128) * 2);
        *(uint16_t *)(sm + OB1 + off) = packh1(eW1[(size_t)(128 + k) * 128 + n]);
    }
    for (int idx = tid; idx < 128 * 128; idx += 256) {
        int n = idx & 127, k = idx >> 7;
        uint32_t off = (k >> 6) * 16384 + swz(n * 128 + (k & 63) * 2);
        *(uint16_t *)(sm + OB2 + off) = packh1(eW2[(size_t)k * 128 + n]);
    }

    const int arow = lane & 15;
    const int ak = (lane >> 4) * 8;
    const int brow = (lane & 7) + 8 * (lane >> 4);
    const int bk = 8 * ((lane >> 3) & 1);

    uint32_t AH[2][4], BH[4][4];
    auto ldA64 = [&](int koff) {
#pragma unroll
        for (int m = 0; m < 2; m++) {
            uint32_t off = swz64((uint32_t)((32 * wm + 16 * m + arow) * 64 + koff * 2));
            ldsm4(AH[m], sbase + OA + off);
        }
    };
    auto ldA128 = [&](uint32_t baseA, int koff) {
#pragma unroll
        for (int m = 0; m < 2; m++) {
            uint32_t off = swz((uint32_t)((32 * wm + 16 * m + arow) * 128 + koff * 2));
            ldsm4(AH[m], baseA + off);
        }
    };
    auto ldB128 = [&](uint32_t baseB, int koff) {
#pragma unroll
        for (int p = 0; p < 4; p++) {
            uint32_t off = swz((uint32_t)((64 * wn + 16 * p + brow) * 128 + koff * 2));
            ldsm4(BH[p], baseB + off);
        }
    };
    auto ldB64 = [&](uint32_t baseB, int koff) {
#pragma unroll
        for (int p = 0; p < 4; p++) {
            uint32_t off = swz64((uint32_t)((64 * wn + 16 * p + brow) * 64 + koff * 2));
            ldsm4(BH[p], baseB + off);
        }
    };

    __syncthreads();  // weights ready

    for (int tile = blockIdx.x; tile < ntiles; tile += gridDim.x) {
        const size_t rowbase = (size_t)tile * 128;
        const int nb0 = tile * 4;

        if (tid < 128) mask_s[tid] = mask[rowbase + tid];

        float acc[2][8][4];
#pragma unroll
        for (int m = 0; m < 2; m++)
#pragma unroll
            for (int nt = 0; nt < 8; nt++)
#pragma unroll
                for (int j = 0; j < 4; j++) acc[m][nt][j] = 0.f;

        // ---- GEMM1: 5 sub-chunks of K=32 ----
#pragma unroll
        for (int s = 0; s < 5; s++) {
            // load + convert this sub-chunk (128 rows x 32 floats)
            {
                float4 v[4];
#pragma unroll
                for (int i = 0; i < 4; i++) {
                    int q = tid + 256 * i;
                    int row = q >> 3, c4 = (q & 7) * 4;
                    const float *src = (s < 4)
                                           ? (h_nei + (rowbase + row) * 128 + s * 32 + c4)
                                           : (e_ij + (rowbase + row) * 32 + c4);
                    v[i] = *(const float4 *)src;
                }
#pragma unroll
                for (int i = 0; i < 4; i++) {
                    int q = tid + 256 * i;
                    int row = q >> 3, c4 = (q & 7) * 4;
                    uint32_t off = swz64((uint32_t)(row * 64 + c4 * 2));
                    *(uint2 *)(sm + OA + off) =
                        make_uint2(packh2(v[i].x, v[i].y), packh2(v[i].z, v[i].w));
                }
            }
            __syncthreads();  // A ready
#pragma unroll
            for (int ks = 0; ks < 2; ks++) {
                const int g = 2 * s + ks;
                ldA64(ks * 16 + ak);
                if (g < 8)
                    ldB128(sbase + OB1 + (g >> 2) * 16384, (g & 3) * 16 + bk);
                else
                    ldB64(sbase + OB1 + 32768, (g - 8) * 16 + bk);
#pragma unroll
                for (int m = 0; m < 2; m++)
#pragma unroll
                    for (int p = 0; p < 4; p++) {
                        mma16816(acc[m][2 * p], AH[m], &BH[p][0]);
                        mma16816(acc[m][2 * p + 1], AH[m], &BH[p][2]);
                    }
            }
            __syncthreads();  // MMA reads done; OA reusable
        }

        // ---- epilogue 1: y = relu(acc + aself) -> Y ----
#pragma unroll
        for (int nt = 0; nt < 8; nt++) {
            int c0 = 64 * wn + 8 * nt + 2 * tig;
            float2 as = *(const float2 *)(g_aself + (size_t)(nb0 + wm) * 128 + c0);
            int cblk = c0 >> 6, ckk = c0 & 63;
#pragma unroll
            for (int m = 0; m < 2; m++) {
                int r = 32 * wm + 16 * m + gid;
                float y00 = fmaxf(acc[m][nt][0] + as.x, 0.f);
                float y01 = fmaxf(acc[m][nt][1] + as.y, 0.f);
                float y10 = fmaxf(acc[m][nt][2] + as.x, 0.f);
                float y11 = fmaxf(acc[m][nt][3] + as.y, 0.f);
                uint32_t off0 = cblk * 16384 + swz((uint32_t)(r * 128 + ckk * 2));
                uint32_t off1 = cblk * 16384 + swz((uint32_t)((r + 8) * 128 + ckk * 2));
                *(uint32_t *)(sm + OY + off0) = packh2(y00, y01);
                *(uint32_t *)(sm + OY + off1) = packh2(y10, y11);
            }
        }
        __syncthreads();  // Y ready

        // ---- GEMM2: K=128, A = Y, B = eW2 ----
#pragma unroll
        for (int m = 0; m < 2; m++)
#pragma unroll
            for (int nt = 0; nt < 8; nt++)
#pragma unroll
                for (int j = 0; j < 4; j++) acc[m][nt][j] = 0.f;

        for (int ks = 0; ks < 8; ks++) {
            const int cb = ks >> 2;
            ldA128(sbase + OY + cb * 16384, (ks & 3) * 16 + ak);
            ldB128(sbase + OB2 + cb * 16384, (ks & 3) * 16 + bk);
#pragma unroll
            for (int m = 0; m < 2; m++)
#pragma unroll
                for (int p = 0; p < 4; p++) {
                    mma16816(acc[m][2 * p], AH[m], &BH[p][0]);
                    mma16816(acc[m][2 * p + 1], AH[m], &BH[p][2]);
                }
        }

        // ---- epilogue 2: z = relu(acc+eb2); g_mi[node] = sum mask*z ----
        {
            float mk[2][2];
#pragma unroll
            for (int m = 0; m < 2; m++) {
                mk[m][0] = mask_s[32 * wm + 16 * m + gid];
                mk[m][1] = mask_s[32 * wm + 16 * m + gid + 8];
            }
#pragma unroll
            for (int nt = 0; nt < 8; nt++) {
                int c0 = 64 * wn + 8 * nt + 2 * tig;
                float2 eb = *(const float2 *)(eb2 + c0);
                float s0 = 0.f, s1 = 0.f;
#pragma unroll
                for (int m = 0; m < 2; m++) {
                    s0 += mk[m][0] * fmaxf(acc[m][nt][0] + eb.x, 0.f) +
                          mk[m][1] * fmaxf(acc[m][nt][2] + eb.x, 0.f);
                    s1 += mk[m][0] * fmaxf(acc[m][nt][1] + eb.y, 0.f) +
                          mk[m][1] * fmaxf(acc[m][nt][3] + eb.y, 0.f);
                }
#pragma unroll
                for (int o = 4; o <= 16; o <<= 1) {
                    s0 += __shfl_xor_sync(0xffffffffu, s0, o);
                    s1 += __shfl_xor_sync(0xffffffffu, s1, o);
                }
                if (lane < 4) {
                    g_mi[(size_t)(nb0 + wm) * 128 + c0] = s0;
                    g_mi[(size_t)(nb0 + wm) * 128 + c0 + 1] = s1;
                }
            }
        }
        __syncthreads();  // ep2 done reading mask_s before next tile rewrites
    }
}

// ---------------------------------------------------------------------------
// Kernel 3: node MLP (fp16 HMMA, staged halves pipeline)
// ---------------------------------------------------------------------------
#define ND_OW1 0        // 65536
#define ND_OW2 65536    // 32768
#define ND_OA  98304    // 65536
#define ND_OST 163840   // 65536 fp32 staging
#define ND_OB1 229376
#define ND_OB2 229888
#define NODE_SMEM 230400

__global__ __launch_bounds__(256, 1) void node_kernel(
    const float *__restrict__ h_self, const float *__restrict__ nW1,
    const float *__restrict__ nb1, const float *__restrict__ nW2,
    const float *__restrict__ nb2, float *__restrict__ out, int ntiles) {
    char *sm = (char *)smem;
    float *b1s = (float *)(sm + ND_OB1);
    float *b2s = (float *)(sm + ND_OB2);
    const int tid = threadIdx.x;
    const int wid = tid >> 5, lane = tid & 31;
    const int wm = wid & 3, wn = wid >> 2;
    const int gid = lane >> 2, tig = lane & 3;
    const uint32_t sbase = smem_u32(sm);

    auto issue_half = [&](int t2, int h) {
        const int row0 = t2 * 128;
        const float *srcb = h ? g_mi : h_self;
#pragma unroll
        for (int i = 0; i < 16; i++) {
            int q = tid + 256 * i;
            int row = q >> 5, c4 = (q & 31) * 4;
            int grow = row0 + row;
            if (grow > B_ - 1) grow = B_ - 1;
            CP_ASYNC16(sbase + ND_OST + q * 16, srcb + (size_t)grow * 128 + c4);
        }
        CP_COMMIT();
    };

    int tile = blockIdx.x;
    if (tile < ntiles) issue_half(tile, 0);

    for (int idx = tid; idx < 256 * 128; idx += 256) {
        int n = idx & 127, k = idx >> 7;
        int c = k >> 6, kk = k & 63;
        uint32_t off = c * 16384 + swz(n * 128 + kk * 2);
        *(uint16_t *)(sm + ND_OW1 + off) = packh1(nW1[(size_t)k * 128 + n]);
    }
    for (int idx = tid; idx < 128 * 128; idx += 256) {
        int n = idx & 127, k = idx >> 7;
        int c = k >> 6, kk = k & 63;
        uint32_t off = c * 16384 + swz(n * 128 + kk * 2);
        *(uint16_t *)(sm + ND_OW2 + off) = packh1(nW2[(size_t)k * 128 + n]);
    }
    if (tid < 128) {
        b1s[tid] = nb1[tid];
        b2s[tid] = nb2[tid];
    }

    const int arow = lane & 15;
    const int ak = (lane >> 4) * 8;
    const int brow = (lane & 7) + 8 * (lane >> 4);
    const int bk = 8 * ((lane >> 3) & 1);

    uint32_t AH[2][4], BH[4][4];
    auto ldA = [&](uint32_t baseA, int koff) {
#pragma unroll
        for (int m = 0; m < 2; m++) {
            uint32_t off = swz((uint32_t)((32 * wm + 16 * m + arow) * 128 + koff * 2));
            ldsm4(AH[m], baseA + off);
        }
    };
    auto ldB = [&](uint32_t baseB, int koff) {
#pragma unroll
        for (int p = 0; p < 4; p++) {
            uint32_t off = swz((uint32_t)((64 * wn + 16 * p + brow) * 128 + koff * 2));
            ldsm4(BH[p], baseB + off);
        }
    };
    auto convert_half = [&](int h) {
#pragma unroll
        for (int i = 0; i < 16; i++) {
            int q = tid + 256 * i;
            int r = q >> 5, c4 = (q & 31) * 4;
            float4 v = *(const float4 *)(sm + ND_OST + q * 16);
            uint32_t off = (2 * h + (c4 >> 6)) * 16384 +
                           swz((uint32_t)(r * 128 + (c4 & 63) * 2));
            *(uint2 *)(sm + ND_OA + off) =
                make_uint2(packh2(v.x, v.y), packh2(v.z, v.w));
        }
    };

    for (; tile < ntiles; tile += gridDim.x) {
        const int row0 = tile * 128;
        __syncthreads();
        CP_WAIT0();
        convert_half(0);
        __syncthreads();
        issue_half(tile, 1);

        float acc[2][8][4];
#pragma unroll
        for (int m = 0; m < 2; m++)
#pragma unroll
            for (int nt = 0; nt < 8; nt++)
#pragma unroll
                for (int j = 0; j < 4; j++) acc[m][nt][j] = 0.f;

        for (int ks = 0; ks < 8; ks++) {
            const int cb = ks >> 2;
            ldA(sbase + ND_OA + cb * 16384, (ks & 3) * 16 + ak);
            ldB(sbase + ND_OW1 + cb * 16384, (ks & 3) * 16 + bk);
#pragma unroll
            for (int m = 0; m < 2; m++)
#pragma unroll
                for (int p = 0; p < 4; p++) {
                    mma16816(acc[m][2 * p], AH[m], &BH[p][0]);
                    mma16816(acc[m][2 * p + 1], AH[m], &BH[p][2]);
                }
        }
        CP_WAIT0();
        convert_half(1);
        __syncthreads();
        if (tile + gridDim.x < ntiles) issue_half(tile + gridDim.x, 0);

        for (int ks = 8; ks < 16; ks++) {
            const int cb = ks >> 2;
            ldA(sbase + ND_OA + cb * 16384, (ks & 3) * 16 + ak);
            ldB(sbase + ND_OW1 + cb * 16384, (ks & 3) * 16 + bk);
#pragma unroll
            for (int m = 0; m < 2; m++)
#pragma unroll
                for (int p = 0; p < 4; p++) {
                    mma16816(acc[m][2 * p], AH[m], &BH[p][0]);
                    mma16816(acc[m][2 * p + 1], AH[m], &BH[p][2]);
                }
        }
        __syncthreads();

#pragma unroll
        for (int nt = 0; nt < 8; nt++) {
            int c0 = 64 * wn + 8 * nt + 2 * tig;
            float bv0 = b1s[c0], bv1 = b1s[c0 + 1];
            int cblk = c0 >> 6, ckk = c0 & 63;
#pragma unroll
            for (int m = 0; m < 2; m++) {
                int r = 32 * wm + 16 * m + gid;
                float y00 = fmaxf(acc[m][nt][0] + bv0, 0.f);
                float y01 = fmaxf(acc[m][nt][1] + bv1, 0.f);
                float y10 = fmaxf(acc[m][nt][2] + bv0, 0.f);
                float y11 = fmaxf(acc[m][nt][3] + bv1, 0.f);
                uint32_t off0 = cblk * 16384 + swz((uint32_t)(r * 128 + ckk * 2));
                uint32_t off1 = cblk * 16384 + swz((uint32_t)((r + 8) * 128 + ckk * 2));
                *(uint32_t *)(sm + ND_OA + off0) = packh2(y00, y01);
                *(uint32_t *)(sm + ND_OA + off1) = packh2(y10, y11);
            }
        }
        __syncthreads();

#pragma unroll
        for (int m = 0; m < 2; m++)
#pragma unroll
            for (int nt = 0; nt < 8; nt++)
#pragma unroll
                for (int j = 0; j < 4; j++) acc[m][nt][j] = 0.f;

        for (int ks = 0; ks < 8; ks++) {
            const int cb = ks >> 2;
            ldA(sbase + ND_OA + cb * 16384, (ks & 3) * 16 + ak);
            ldB(sbase + ND_OW2 + cb * 16384, (ks & 3) * 16 + bk);
#pragma unroll
            for (int m = 0; m < 2; m++)
#pragma unroll
                for (int p = 0; p < 4; p++) {
                    mma16816(acc[m][2 * p], AH[m], &BH[p][0]);
                    mma16816(acc[m][2 * p + 1], AH[m], &BH[p][2]);
                }
        }

#pragma unroll
        for (int nt = 0; nt < 8; nt++) {
            int c0 = 64 * wn + 8 * nt + 2 * tig;
            float bv0 = b2s[c0], bv1 = b2s[c0 + 1];
#pragma unroll
            for (int m = 0; m < 2; m++) {
                int r = 32 * wm + 16 * m + gid;
                int grow = row0 + r;
                if (grow < B_) {
                    float2 v = make_float2(fmaxf(acc[m][nt][0] + bv0, 0.f),
                                           fmaxf(acc[m][nt][1] + bv1, 0.f));
                    *(float2 *)(out + (size_t)grow * 128 + c0) = v;
                }
                if (grow + 8 < B_) {
                    float2 v = make_float2(fmaxf(acc[m][nt][2] + bv0, 0.f),
                                           fmaxf(acc[m][nt][3] + bv1, 0.f));
                    *(float2 *)(out + (size_t)(grow + 8) * 128 + c0) = v;
                }
            }
        }
    }
}

// ---------------------------------------------------------------------------
extern "C" void kernel_launch(void *const *d_in, const int *in_sizes, int n_in,
                              void *d_out, int out_size) {
    const float *h_self = (const float *)d_in[0];
    const float *h_nei = (const float *)d_in[1];
    const float *e_ij = (const float *)d_in[2];
    const float *mask = (const float *)d_in[3];
    const float *eW1 = (const float *)d_in[4];
    const float *eb1 = (const float *)d_in[5];
    const float *eW2 = (const float *)d_in[6];
    const float *eb2 = (const float *)d_in[7];
    const float *nW1 = (const float *)d_in[8];
    const float *nb1 = (const float *)d_in[9];
    const float *nW2 = (const float *)d_in[10];
    const float *nb2 = (const float *)d_in[11];
    float *out = (float *)d_out;

    cudaFuncSetAttribute(self_kernel, cudaFuncAttributeMaxDynamicSharedMemorySize,
                         SELF_SMEM);
    cudaFuncSetAttribute(edge_mma_kernel,
                         cudaFuncAttributeMaxDynamicSharedMemorySize, EDGE_SMEM);
    cudaFuncSetAttribute(node_kernel, cudaFuncAttributeMaxDynamicSharedMemorySize,
                         NODE_SMEM);

    int dev = 0, nsm = 148;
    cudaGetDevice(&dev);
    cudaDeviceGetAttribute(&nsm, cudaDevAttrMultiProcessorCount, dev);

    const int tilesAC = (B_ + 127) / 128;   // 391
    const int ntilesB = B_ * K_ / 128;      // 12500

    self_kernel<<<nsm, 256, SELF_SMEM>>>(h_self, eW1, eb1, tilesAC);
    edge_mma_kernel<<<2 * nsm, 256, EDGE_SMEM>>>(h_nei, e_ij, mask, eW1, eW2, eb2,
                                                 ntilesB);
    node_kernel<<<nsm, 256, NODE_SMEM>>>(h_self, nW1, nb1, nW2, nb2, out, tilesAC);
}

// round 17
// speedup vs baseline: 1.2099x; 1.2099x over previous
#include <cuda_runtime.h>
#include <cuda_fp16.h>
#include <cstdint>
#include <cstddef>

// ---------------------------------------------------------------------------
// MPNN layer, fp32.  B=50000, K=32, D=128, E=32.  ALL GEMMs fp16 HMMA.
// Edge path is MASK-COMPACTED: only active neighbor rows (mask=1) flow
// through the edge MLP, in 8-row node-aligned segments.
// ---------------------------------------------------------------------------

#define B_  50000
#define K_  32
#define D_  128
#define E_  32
#define NBLK 196            // ceil(50000/256)

__device__ float g_aself[(size_t)B_ * D_];
__device__ float g_mi[(size_t)B_ * D_];
__device__ int   g_pseg[(B_ + 255) & ~255];
__device__ int   g_bsum[256];
__device__ int   g_boff[256];
__device__ int   g_total[2];                 // [0]=segments S, [1]=ntiles
__device__ int   g_ridx[(size_t)B_ * K_ + 512];

// ======================= helpers ===========================================
__device__ __forceinline__ uint32_t smem_u32(const void* p) {
    uint32_t a;
    asm("{ .reg .u64 t; cvta.to.shared.u64 t, %1; cvt.u32.u64 %0, t; }"
        : "=r"(a) : "l"(p));
    return a;
}
__device__ __forceinline__ uint32_t swz(uint32_t b) { return b ^ ((b >> 3) & 0x70); }
__device__ __forceinline__ uint32_t swz64(uint32_t b) { return b ^ ((b >> 3) & 0x30); }
__device__ __forceinline__ uint32_t packh2(float a, float b) {
    uint32_t r;
    asm("cvt.rn.f16x2.f32 %0, %1, %2;" : "=r"(r) : "f"(b), "f"(a));
    return r;
}
__device__ __forceinline__ uint16_t packh1(float a) {
    uint16_t r;
    asm("cvt.rn.f16.f32 %0, %1;" : "=h"(r) : "f"(a));
    return r;
}
__device__ __forceinline__ void ldsm4(uint32_t* r, uint32_t addr) {
    asm volatile("ldmatrix.sync.aligned.m8n8.x4.shared.b16 {%0,%1,%2,%3}, [%4];"
                 : "=r"(r[0]), "=r"(r[1]), "=r"(r[2]), "=r"(r[3]) : "r"(addr));
}
__device__ __forceinline__ void mma16816(float* d, const uint32_t* a, const uint32_t* b) {
    asm("mma.sync.aligned.m16n8k16.row.col.f32.f16.f16.f32 "
        "{%0,%1,%2,%3}, {%4,%5,%6,%7}, {%8,%9}, {%0,%1,%2,%3};"
        : "+f"(d[0]), "+f"(d[1]), "+f"(d[2]), "+f"(d[3])
        : "r"(a[0]), "r"(a[1]), "r"(a[2]), "r"(a[3]), "r"(b[0]), "r"(b[1]));
}
#define CP_ASYNC16(dst, src) \
    asm volatile("cp.async.cg.shared.global [%0], [%1], 16;" :: "r"(dst), "l"(src))
#define CP_COMMIT() asm volatile("cp.async.commit_group;" ::: "memory")
#define CP_WAIT0()  asm volatile("cp.async.wait_group 0;" ::: "memory")
#define CP_WAIT1()  asm volatile("cp.async.wait_group 1;" ::: "memory")

extern __shared__ float smem[];

// ---------------------------------------------------------------------------
// Prep 1: per-node active count -> pseg; block sums; zero g_mi.
// ---------------------------------------------------------------------------
__global__ __launch_bounds__(256, 1) void prep1_kernel(const float *__restrict__ mask) {
    __shared__ int s[256];
    const int tid = threadIdx.x;
    const int n = blockIdx.x * 256 + tid;
    int pseg = 0;
    if (n < B_) {
        int na = 0;
        for (int k = 0; k < 32; k++) na += (mask[(size_t)n * 32 + k] > 0.5f) ? 1 : 0;
        pseg = (na + 7) >> 3;
        g_pseg[n] = pseg;
    }
    s[tid] = pseg;
    __syncthreads();
    for (int off = 1; off < 256; off <<= 1) {
        int t = (tid >= off) ? s[tid - off] : 0;
        __syncthreads();
        s[tid] += t;
        __syncthreads();
    }
    if (tid == 0) g_bsum[blockIdx.x] = s[255];

    // zero g_mi (coalesced float4)
    float4 *p = (float4 *)g_mi;
    const int tot = B_ * 128 / 4;
    for (int i = blockIdx.x * 256 + tid; i < tot; i += gridDim.x * 256)
        p[i] = make_float4(0.f, 0.f, 0.f, 0.f);
}

// ---------------------------------------------------------------------------
// Prep 2: scan block sums; totals; fill ridx tail padding.
// ---------------------------------------------------------------------------
__global__ __launch_bounds__(256, 1) void prep2_kernel() {
    __shared__ int s[256];
    const int tid = threadIdx.x;
    int v = (tid < NBLK) ? g_bsum[tid] : 0;
    s[tid] = v;
    __syncthreads();
    for (int off = 1; off < 256; off <<= 1) {
        int t = (tid >= off) ? s[tid - off] : 0;
        __syncthreads();
        s[tid] += t;
        __syncthreads();
    }
    g_boff[tid] = s[tid] - v;  // exclusive
    int S = s[255];
    int ntiles = (S * 8 + 255) >> 8;
    if (tid == 0) {
        g_total[0] = S;
        g_total[1] = ntiles;
    }
    __syncthreads();
    for (int i = S * 8 + tid; i < ntiles * 256; i += 256)
        g_ridx[i] = (int)0x80000000;
}

// ---------------------------------------------------------------------------
// Prep 3: write compacted row indices (8-row segments, node aligned).
// ---------------------------------------------------------------------------
__global__ __launch_bounds__(256, 1) void prep3_kernel(const float *__restrict__ mask) {
    __shared__ int s[256];
    const int tid = threadIdx.x;
    const int n = blockIdx.x * 256 + tid;
    int pseg = 0, na = 0;
    if (n < B_) {
        for (int k = 0; k < 32; k++) na += (mask[(size_t)n * 32 + k] > 0.5f) ? 1 : 0;
        pseg = (na + 7) >> 3;
    }
    s[tid] = pseg;
    __syncthreads();
    for (int off = 1; off < 256; off <<= 1) {
        int t = (tid >= off) ? s[tid - off] : 0;
        __syncthreads();
        s[tid] += t;
        __syncthreads();
    }
    if (n < B_ && pseg > 0) {
        int seg0 = g_boff[blockIdx.x] + s[tid] - pseg;  // exclusive local
        int base = seg0 * 8;
        int i = 0;
        for (int k = 0; k < 32; k++)
            if (mask[(size_t)n * 32 + k] > 0.5f) g_ridx[base + (i++)] = n * 32 + k;
        for (; i < pseg * 8; i++) g_ridx[base + i] = (int)0x80000000 | (n * 32);
    }
}

// ---------------------------------------------------------------------------
// Kernel 1: a_self = h_self @ eW1[0:128,:] + eb1  (fp16 HMMA, cp.async pipe)
// ---------------------------------------------------------------------------
#define SW_OW 0
#define SW_OST 32768
#define SW_OA 98304
#define SW_OEB 131072
#define SELF_SMEM 131584

__global__ __launch_bounds__(256, 1) void self_kernel(
    const float *__restrict__ h_self, const float *__restrict__ eW1,
    const float *__restrict__ eb1, int ntiles) {
    char *sm = (char *)smem;
    float *ebs = (float *)(sm + SW_OEB);
    const int tid = threadIdx.x;
    const int wid = tid >> 5, lane = tid & 31;
    const int wm = wid & 3, wn = wid >> 2;
    const int gid = lane >> 2, tig = lane & 3;
    const uint32_t sbase = smem_u32(sm);

    auto issue_dma = [&](int t2) {
        const int row0 = t2 * 128;
#pragma unroll
        for (int i = 0; i < 16; i++) {
            int q = tid + 256 * i;
            int row = q >> 5, c4 = (q & 31) * 4;
            int grow = row0 + row;
            if (grow > B_ - 1) grow = B_ - 1;
            CP_ASYNC16(sbase + SW_OST + q * 16, h_self + (size_t)grow * 128 + c4);
        }
        CP_COMMIT();
    };

    int tile = blockIdx.x;
    if (tile < ntiles) issue_dma(tile);

    for (int idx = tid; idx < 128 * 128; idx += 256) {
        int n = idx & 127, k = idx >> 7;
        int c = k >> 6, kk = k & 63;
        uint32_t off = c * 16384 + swz(n * 128 + kk * 2);
        *(uint16_t *)(sm + SW_OW + off) = packh1(eW1[(size_t)k * 128 + n]);
    }
    if (tid < 128) ebs[tid] = eb1[tid];

    const int arow = lane & 15;
    const int ak = (lane >> 4) * 8;
    const int brow = (lane & 7) + 8 * (lane >> 4);
    const int bk = 8 * ((lane >> 3) & 1);

    uint32_t AH[2][2][4], BH[2][4][4];
    auto ldA = [&](uint32_t baseA, int koff, uint32_t (&AHb)[2][4]) {
#pragma unroll
        for (int m = 0; m < 2; m++) {
            uint32_t off = swz((uint32_t)((32 * wm + 16 * m + arow) * 128 + koff * 2));
            ldsm4(AHb[m], baseA + off);
        }
    };
    auto ldB = [&](uint32_t baseB, int koff, uint32_t (&BHb)[4][4]) {
#pragma unroll
        for (int p = 0; p < 4; p++) {
            uint32_t off = swz((uint32_t)((64 * wn + 16 * p + brow) * 128 + koff * 2));
            ldsm4(BHb[p], baseB + off);
        }
    };

    for (; tile < ntiles; tile += gridDim.x) {
        const int row0 = tile * 128;
        __syncthreads();
        CP_WAIT0();
#pragma unroll
        for (int i = 0; i < 16; i++) {
            int q = tid + 256 * i;
            int r = q >> 5, c4 = (q & 31) * 4;
            float4 v = *(const float4 *)(sm + SW_OST + q * 16);
            uint32_t off = (c4 >> 6) * 16384 + swz((uint32_t)(r * 128 + (c4 & 63) * 2));
            *(uint2 *)(sm + SW_OA + off) =
                make_uint2(packh2(v.x, v.y), packh2(v.z, v.w));
        }
        __syncthreads();
        if (tile + gridDim.x < ntiles) issue_dma(tile + gridDim.x);

        float acc[2][8][4];
#pragma unroll
        for (int m = 0; m < 2; m++)
#pragma unroll
            for (int nt = 0; nt < 8; nt++)
#pragma unroll
                for (int j = 0; j < 4; j++) acc[m][nt][j] = 0.f;

        ldA(sbase + SW_OA, ak, AH[0]);
        ldB(sbase + SW_OW, bk, BH[0]);
#pragma unroll
        for (int ks = 0; ks < 8; ks++) {
            const int cur = ks & 1, nxt = cur ^ 1;
            if (ks + 1 < 8) {
                const int k2 = ks + 1, cb = k2 >> 2;
                ldA(sbase + SW_OA + cb * 16384, (k2 & 3) * 16 + ak, AH[nxt]);
                ldB(sbase + SW_OW + cb * 16384, (k2 & 3) * 16 + bk, BH[nxt]);
            }
#pragma unroll
            for (int m = 0; m < 2; m++)
#pragma unroll
                for (int p = 0; p < 4; p++) {
                    mma16816(acc[m][2 * p], AH[cur][m], &BH[cur][p][0]);
                    mma16816(acc[m][2 * p + 1], AH[cur][m], &BH[cur][p][2]);
                }
        }

#pragma unroll
        for (int nt = 0; nt < 8; nt++) {
            int c0 = 64 * wn + 8 * nt + 2 * tig;
            float bv0 = ebs[c0], bv1 = ebs[c0 + 1];
#pragma unroll
            for (int m = 0; m < 2; m++) {
                int r = 32 * wm + 16 * m + gid;
                int grow = row0 + r;
                if (grow < B_) {
                    float2 v = make_float2(acc[m][nt][0] + bv0, acc[m][nt][1] + bv1);
                    *(float2 *)(g_aself + (size_t)grow * 128 + c0) = v;
                }
                if (grow + 8 < B_) {
                    float2 v = make_float2(acc[m][nt][2] + bv0, acc[m][nt][3] + bv1);
                    *(float2 *)(g_aself + (size_t)(grow + 8) * 128 + c0) = v;
                }
            }
        }
    }
}

// ---------------------------------------------------------------------------
// Kernel 2: edge MLP on COMPACTED rows. 512 thr, 256-row tiles, 2-deep pipe.
// ---------------------------------------------------------------------------
#define OB1 0          // eW1[128:288]^T : 3 x 16384 = 49152
#define OB2 49152      // eW2^T : 2 x 16384 = 32768
#define OST 81920      // dual fp32 staging 2 x 32768 (union: Y 65536)
#define OA  147456     // dual fp16 A sub-chunk 2 x 16384 (SW64)
#define ORIDX 180224   // 256 ints
#define EDGE_SMEM 181248

__global__ __launch_bounds__(512, 1) void edge_mma_kernel(
    const float *__restrict__ h_nei, const float *__restrict__ e_ij,
    const float *__restrict__ eW1, const float *__restrict__ eW2,
    const float *__restrict__ eb2) {
    char *sm = (char *)smem;
    int *ridx_s = (int *)(sm + ORIDX);
    const int tid = threadIdx.x;
    const int wid = tid >> 5, lane = tid & 31;
    const int wm = wid & 7, wn = wid >> 3;   // 8 M-groups x 2 N-groups
    const int gid = lane >> 2, tig = lane & 3;
    const uint32_t sbase = smem_u32(sm);
    const int ntiles = *(volatile int *)&g_total[1];

    // DMA one K32 sub-chunk (256 gathered rows x 32 floats) into stage[s&1]
    auto issue_sub = [&](int s) {
        const uint32_t dst0 = sbase + OST + (uint32_t)(s & 1) * 32768;
#pragma unroll
        for (int i = 0; i < 4; i++) {
            int q = tid + 512 * i;
            int row = q >> 3, c4 = (q & 7) * 4;
            size_t r = (size_t)(ridx_s[row] & 0x7fffffff);
            const float *src = (s < 4) ? (h_nei + r * 128 + s * 32 + c4)
                                       : (e_ij + r * 32 + c4);
            CP_ASYNC16(dst0 + q * 16, src);
        }
        CP_COMMIT();
    };

    int tile = blockIdx.x;
    if (tile < ntiles && tid < 256) ridx_s[tid] = g_ridx[(size_t)tile * 256 + tid];
    __syncthreads();
    if (tile < ntiles) {
        issue_sub(0);
        issue_sub(1);
    }

    // one-time: weights -> fp16 [n][k] blocked (overlaps prologue DMA)
    for (int idx = tid; idx < 160 * 128; idx += 512) {
        int n = idx & 127, k = idx >> 7;
        int c = k >> 6, kk = k & 63;
        uint32_t off = c * 16384 + swz(n * 128 + kk * 2);
        *(uint16_t *)(sm + OB1 + off) = packh1(eW1[(size_t)(128 + k) * 128 + n]);
    }
    for (int idx = tid; idx < 128 * 128; idx += 512) {
        int n = idx & 127, k = idx >> 7;
        int c = k >> 6, kk = k & 63;
        uint32_t off = c * 16384 + swz(n * 128 + kk * 2);
        *(uint16_t *)(sm + OB2 + off) = packh1(eW2[(size_t)k * 128 + n]);
    }

    const int arow = lane & 15;
    const int ak = (lane >> 4) * 8;
    const int brow = (lane & 7) + 8 * (lane >> 4);
    const int bk = 8 * ((lane >> 3) & 1);

    uint32_t AH[2][4], BH[4][4];
    auto ldA64 = [&](uint32_t baseA, int koff) {
#pragma unroll
        for (int m = 0; m < 2; m++) {
            uint32_t off = swz64((uint32_t)((32 * wm + 16 * m + arow) * 64 + koff * 2));
            ldsm4(AH[m], baseA + off);
        }
    };
    auto ldA128 = [&](uint32_t baseA, int koff) {
#pragma unroll
        for (int m = 0; m < 2; m++) {
            uint32_t off = swz((uint32_t)((32 * wm + 16 * m + arow) * 128 + koff * 2));
            ldsm4(AH[m], baseA + off);
        }
    };
    auto ldB128 = [&](uint32_t baseB, int koff) {
#pragma unroll
        for (int p = 0; p < 4; p++) {
            uint32_t off = swz((uint32_t)((64 * wn + 16 * p + brow) * 128 + koff * 2));
            ldsm4(BH[p], baseB + off);
        }
    };

    for (; tile < ntiles; tile += gridDim.x) {
        __syncthreads();  // prev tile fully done (weights on iter 0)

        float acc[2][8][4];
#pragma unroll
        for (int m = 0; m < 2; m++)
#pragma unroll
            for (int nt = 0; nt < 8; nt++)
#pragma unroll
                for (int j = 0; j < 4; j++) acc[m][nt][j] = 0.f;

        // ---- GEMM1: 5 sub-chunks of K=32, 2-deep DMA pipeline ----
#pragma unroll
        for (int s = 0; s < 5; s++) {
            if (s < 4) { CP_WAIT1(); } else { CP_WAIT0(); }
            {
                const uint32_t st0 = OST + (uint32_t)(s & 1) * 32768;
                const uint32_t ad0 = OA + (uint32_t)(s & 1) * 16384;
#pragma unroll
                for (int i = 0; i < 4; i++) {
                    int q = tid + 512 * i;
                    int row = q >> 3, c4 = (q & 7) * 4;
                    float4 v = *(const float4 *)(sm + st0 + q * 16);
                    uint32_t off = swz64((uint32_t)(row * 64 + c4 * 2));
                    *(uint2 *)(sm + ad0 + off) =
                        make_uint2(packh2(v.x, v.y), packh2(v.z, v.w));
                }
            }
            __syncthreads();  // A[s&1] ready; stage[s&1] free
            if (s < 3) issue_sub(s + 2);
            const uint32_t aB = sbase + OA + (uint32_t)(s & 1) * 16384;
#pragma unroll
            for (int ks = 0; ks < 2; ks++) {
                const int g = 2 * s + ks;
                ldA64(aB, ks * 16 + ak);
                ldB128(sbase + OB1 + (g >> 2) * 16384, (g & 3) * 16 + bk);
#pragma unroll
                for (int m = 0; m < 2; m++)
#pragma unroll
                    for (int p = 0; p < 4; p++) {
                        mma16816(acc[m][2 * p], AH[m], &BH[p][0]);
                        mma16816(acc[m][2 * p + 1], AH[m], &BH[p][2]);
                    }
            }
        }

        // per-segment node ids + pad weights (segments j=0..3 of this M-group)
        int ndf[4];
        float wf[4];
#pragma unroll
        for (int j = 0; j < 4; j++) {
            int raw = ridx_s[32 * wm + 8 * j + gid];
            ndf[j] = (raw & 0x7fffffff) >> 5;
            wf[j] = (raw < 0) ? 0.f : 1.f;
        }

        // ---- epilogue 1: y = relu(acc + aself[node(row)]) -> Y ----
#pragma unroll
        for (int nt = 0; nt < 8; nt++) {
            int c0 = 64 * wn + 8 * nt + 2 * tig;
            int ckk = c0 & 63;
#pragma unroll
            for (int m = 0; m < 2; m++) {
                float2 a0 = *(const float2 *)(g_aself + (size_t)ndf[2 * m] * 128 + c0);
                float2 a1 =
                    *(const float2 *)(g_aself + (size_t)ndf[2 * m + 1] * 128 + c0);
                int r = 32 * wm + 16 * m + gid;
                float y00 = fmaxf(acc[m][nt][0] + a0.x, 0.f);
                float y01 = fmaxf(acc[m][nt][1] + a0.y, 0.f);
                float y10 = fmaxf(acc[m][nt][2] + a1.x, 0.f);
                float y11 = fmaxf(acc[m][nt][3] + a1.y, 0.f);
                uint32_t off0 = wn * 32768 + swz((uint32_t)(r * 128 + ckk * 2));
                uint32_t off1 = wn * 32768 + swz((uint32_t)((r + 8) * 128 + ckk * 2));
                *(uint32_t *)(sm + OST + off0) = packh2(y00, y01);
                *(uint32_t *)(sm + OST + off1) = packh2(y10, y11);
            }
        }
        __syncthreads();  // Y ready

        // ---- GEMM2: K=128, A = Y, B = eW2 ----
#pragma unroll
        for (int m = 0; m < 2; m++)
#pragma unroll
            for (int nt = 0; nt < 8; nt++)
#pragma unroll
                for (int j = 0; j < 4; j++) acc[m][nt][j] = 0.f;

        for (int ks = 0; ks < 8; ks++) {
            const int cb = ks >> 2;
            ldA128(sbase + OST + cb * 32768, (ks & 3) * 16 + ak);
            ldB128(sbase + OB2 + cb * 16384, (ks & 3) * 16 + bk);
#pragma unroll
            for (int m = 0; m < 2; m++)
#pragma unroll
                for (int p = 0; p < 4; p++) {
                    mma16816(acc[m][2 * p], AH[m], &BH[p][0]);
                    mma16816(acc[m][2 * p + 1], AH[m], &BH[p][2]);
                }
        }
        __syncthreads();  // GEMM2 reads of Y done -> stage reusable

        // load next tile's ridx, then prefetch its first two sub-chunks
        if (tile + gridDim.x < ntiles) {
            if (tid < 256)
                ridx_s[tid] = g_ridx[(size_t)(tile + gridDim.x) * 256 + tid];
            __syncthreads();
            issue_sub(0);
            issue_sub(1);
        } else {
            __syncthreads();
        }

        // ---- epilogue 2: per-segment butterfly; RED into g_mi ----
#pragma unroll
        for (int nt = 0; nt < 8; nt++) {
            int c0 = 64 * wn + 8 * nt + 2 * tig;
            float2 eb = *(const float2 *)(eb2 + c0);
            float s0v[4], s1v[4];
#pragma unroll
            for (int j = 0; j < 4; j++) {
                int m = j >> 1, h = j & 1;
                s0v[j] = wf[j] * fmaxf(acc[m][nt][2 * h] + eb.x, 0.f);
                s1v[j] = wf[j] * fmaxf(acc[m][nt][2 * h + 1] + eb.y, 0.f);
#pragma unroll
                for (int o = 4; o <= 16; o <<= 1) {
                    s0v[j] += __shfl_xor_sync(0xffffffffu, s0v[j], o);
                    s1v[j] += __shfl_xor_sync(0xffffffffu, s1v[j], o);
                }
            }
            if (gid < 4) {
                const int j = gid;
                bool first = true;
                float t0 = 0.f, t1 = 0.f;
#pragma unroll
                for (int jj = 0; jj < 4; jj++)
                    if (ndf[jj] == ndf[j]) {
                        if (jj < j) first = false;
                        t0 += s0v[jj];
                        t1 += s1v[jj];
                    }
                if (first) {
                    atomicAdd(&g_mi[(size_t)ndf[j] * 128 + c0], t0);
                    atomicAdd(&g_mi[(size_t)ndf[j] * 128 + c0 + 1], t1);
                }
            }
        }
    }
}

// ---------------------------------------------------------------------------
// Kernel 3: node MLP (fp16 HMMA, staged halves pipeline)
// ---------------------------------------------------------------------------
#define ND_OW1 0
#define ND_OW2 65536
#define ND_OA  98304
#define ND_OST 163840
#define ND_OB1 229376
#define ND_OB2 229888
#define NODE_SMEM 230400

__global__ __launch_bounds__(256, 1) void node_kernel(
    const float *__restrict__ h_self, const float *__restrict__ nW1,
    const float *__restrict__ nb1, const float *__restrict__ nW2,
    const float *__restrict__ nb2, float *__restrict__ out, int ntiles) {
    char *sm = (char *)smem;
    float *b1s = (float *)(sm + ND_OB1);
    float *b2s = (float *)(sm + ND_OB2);
    const int tid = threadIdx.x;
    const int wid = tid >> 5, lane = tid & 31;
    const int wm = wid & 3, wn = wid >> 2;
    const int gid = lane >> 2, tig = lane & 3;
    const uint32_t sbase = smem_u32(sm);

    auto issue_half = [&](int t2, int h) {
        const int row0 = t2 * 128;
        const float *srcb = h ? g_mi : h_self;
#pragma unroll
        for (int i = 0; i < 16; i++) {
            int q = tid + 256 * i;
            int row = q >> 5, c4 = (q & 31) * 4;
            int grow = row0 + row;
            if (grow > B_ - 1) grow = B_ - 1;
            CP_ASYNC16(sbase + ND_OST + q * 16, srcb + (size_t)grow * 128 + c4);
        }
        CP_COMMIT();
    };

    int tile = blockIdx.x;
    if (tile < ntiles) issue_half(tile, 0);

    for (int idx = tid; idx < 256 * 128; idx += 256) {
        int n = idx & 127, k = idx >> 7;
        int c = k >> 6, kk = k & 63;
        uint32_t off = c * 16384 + swz(n * 128 + kk * 2);
        *(uint16_t *)(sm + ND_OW1 + off) = packh1(nW1[(size_t)k * 128 + n]);
    }
    for (int idx = tid; idx < 128 * 128; idx += 256) {
        int n = idx & 127, k = idx >> 7;
        int c = k >> 6, kk = k & 63;
        uint32_t off = c * 16384 + swz(n * 128 + kk * 2);
        *(uint16_t *)(sm + ND_OW2 + off) = packh1(nW2[(size_t)k * 128 + n]);
    }
    if (tid < 128) {
        b1s[tid] = nb1[tid];
        b2s[tid] = nb2[tid];
    }

    const int arow = lane & 15;
    const int ak = (lane >> 4) * 8;
    const int brow = (lane & 7) + 8 * (lane >> 4);
    const int bk = 8 * ((lane >> 3) & 1);

    uint32_t AH[2][4], BH[4][4];
    auto ldA = [&](uint32_t baseA, int koff) {
#pragma unroll
        for (int m = 0; m < 2; m++) {
            uint32_t off = swz((uint32_t)((32 * wm + 16 * m + arow) * 128 + koff * 2));
            ldsm4(AH[m], baseA + off);
        }
    };
    auto ldB = [&](uint32_t baseB, int koff) {
#pragma unroll
        for (int p = 0; p < 4; p++) {
            uint32_t off = swz((uint32_t)((64 * wn + 16 * p + brow) * 128 + koff * 2));
            ldsm4(BH[p], baseB + off);
        }
    };
    auto convert_half = [&](int h) {
#pragma unroll
        for (int i = 0; i < 16; i++) {
            int q = tid + 256 * i;
            int r = q >> 5, c4 = (q & 31) * 4;
            float4 v = *(const float4 *)(sm + ND_OST + q * 16);
            uint32_t off = (2 * h + (c4 >> 6)) * 16384 +
                           swz((uint32_t)(r * 128 + (c4 & 63) * 2));
            *(uint2 *)(sm + ND_OA + off) =
                make_uint2(packh2(v.x, v.y), packh2(v.z, v.w));
        }
    };

    for (; tile < ntiles; tile += gridDim.x) {
        const int row0 = tile * 128;
        __syncthreads();
        CP_WAIT0();
        convert_half(0);
        __syncthreads();
        issue_half(tile, 1);

        float acc[2][8][4];
#pragma unroll
        for (int m = 0; m < 2; m++)
#pragma unroll
            for (int nt = 0; nt < 8; nt++)
#pragma unroll
                for (int j = 0; j < 4; j++) acc[m][nt][j] = 0.f;

        for (int ks = 0; ks < 8; ks++) {
            const int cb = ks >> 2;
            ldA(sbase + ND_OA + cb * 16384, (ks & 3) * 16 + ak);
            ldB(sbase + ND_OW1 + cb * 16384, (ks & 3) * 16 + bk);
#pragma unroll
            for (int m = 0; m < 2; m++)
#pragma unroll
                for (int p = 0; p < 4; p++) {
                    mma16816(acc[m][2 * p], AH[m], &BH[p][0]);
                    mma16816(acc[m][2 * p + 1], AH[m], &BH[p][2]);
                }
        }
        CP_WAIT0();
        convert_half(1);
        __syncthreads();
        if (tile + gridDim.x < ntiles) issue_half(tile + gridDim.x, 0);

        for (int ks = 8; ks < 16; ks++) {
            const int cb = ks >> 2;
            ldA(sbase + ND_OA + cb * 16384, (ks & 3) * 16 + ak);
            ldB(sbase + ND_OW1 + cb * 16384, (ks & 3) * 16 + bk);
#pragma unroll
            for (int m = 0; m < 2; m++)
#pragma unroll
                for (int p = 0; p < 4; p++) {
                    mma16816(acc[m][2 * p], AH[m], &BH[p][0]);
                    mma16816(acc[m][2 * p + 1], AH[m], &BH[p][2]);
                }
        }
        __syncthreads();

#pragma unroll
        for (int nt = 0; nt < 8; nt++) {
            int c0 = 64 * wn + 8 * nt + 2 * tig;
            float bv0 = b1s[c0], bv1 = b1s[c0 + 1];
            int cblk = c0 >> 6, ckk = c0 & 63;
#pragma unroll
            for (int m = 0; m < 2; m++) {
                int r = 32 * wm + 16 * m + gid;
                float y00 = fmaxf(acc[m][nt][0] + bv0, 0.f);
                float y01 = fmaxf(acc[m][nt][1] + bv1, 0.f);
                float y10 = fmaxf(acc[m][nt][2] + bv0, 0.f);
                float y11 = fmaxf(acc[m][nt][3] + bv1, 0.f);
                uint32_t off0 = cblk * 16384 + swz((uint32_t)(r * 128 + ckk * 2));
                uint32_t off1 = cblk * 16384 + swz((uint32_t)((r + 8) * 128 + ckk * 2));
                *(uint32_t *)(sm + ND_OA + off0) = packh2(y00, y01);
                *(uint32_t *)(sm + ND_OA + off1) = packh2(y10, y11);
            }
        }
        __syncthreads();

#pragma unroll
        for (int m = 0; m < 2; m++)
#pragma unroll
            for (int nt = 0; nt < 8; nt++)
#pragma unroll
                for (int j = 0; j < 4; j++) acc[m][nt][j] = 0.f;

        for (int ks = 0; ks < 8; ks++) {
            const int cb = ks >> 2;
            ldA(sbase + ND_OA + cb * 16384, (ks & 3) * 16 + ak);
            ldB(sbase + ND_OW2 + cb * 16384, (ks & 3) * 16 + bk);
#pragma unroll
            for (int m = 0; m < 2; m++)
#pragma unroll
                for (int p = 0; p < 4; p++) {
                    mma16816(acc[m][2 * p], AH[m], &BH[p][0]);
                    mma16816(acc[m][2 * p + 1], AH[m], &BH[p][2]);
                }
        }

#pragma unroll
        for (int nt = 0; nt < 8; nt++) {
            int c0 = 64 * wn + 8 * nt + 2 * tig;
            float bv0 = b2s[c0], bv1 = b2s[c0 + 1];
#pragma unroll
            for (int m = 0; m < 2; m++) {
                int r = 32 * wm + 16 * m + gid;
                int grow = row0 + r;
                if (grow < B_) {
                    float2 v = make_float2(fmaxf(acc[m][nt][0] + bv0, 0.f),
                                           fmaxf(acc[m][nt][1] + bv1, 0.f));
                    *(float2 *)(out + (size_t)grow * 128 + c0) = v;
                }
                if (grow + 8 < B_) {
                    float2 v = make_float2(fmaxf(acc[m][nt][2] + bv0, 0.f),
                                           fmaxf(acc[m][nt][3] + bv1, 0.f));
                    *(float2 *)(out + (size_t)(grow + 8) * 128 + c0) = v;
                }
            }
        }
    }
}

// ---------------------------------------------------------------------------
extern "C" void kernel_launch(void *const *d_in, const int *in_sizes, int n_in,
                              void *d_out, int out_size) {
    const float *h_self = (const float *)d_in[0];
    const float *h_nei = (const float *)d_in[1];
    const float *e_ij = (const float *)d_in[2];
    const float *mask = (const float *)d_in[3];
    const float *eW1 = (const float *)d_in[4];
    const float *eb1 = (const float *)d_in[5];
    const float *eW2 = (const float *)d_in[6];
    const float *eb2 = (const float *)d_in[7];
    const float *nW1 = (const float *)d_in[8];
    const float *nb1 = (const float *)d_in[9];
    const float *nW2 = (const float *)d_in[10];
    const float *nb2 = (const float *)d_in[11];
    float *out = (float *)d_out;

    cudaFuncSetAttribute(self_kernel, cudaFuncAttributeMaxDynamicSharedMemorySize,
                         SELF_SMEM);
    cudaFuncSetAttribute(edge_mma_kernel,
                         cudaFuncAttributeMaxDynamicSharedMemorySize, EDGE_SMEM);
    cudaFuncSetAttribute(node_kernel, cudaFuncAttributeMaxDynamicSharedMemorySize,
                         NODE_SMEM);

    int dev = 0, nsm = 148;
    cudaGetDevice(&dev);
    cudaDeviceGetAttribute(&nsm, cudaDevAttrMultiProcessorCount, dev);

    const int tilesAC = (B_ + 127) / 128;  // 391

    prep1_kernel<<<NBLK, 256>>>(mask);
    prep2_kernel<<<1, 256>>>();
    prep3_kernel<<<NBLK, 256>>>(mask);
    self_kernel<<<nsm, 256, SELF_SMEM>>>(h_self, eW1, eb1, tilesAC);
    edge_mma_kernel<<<nsm, 512, EDGE_SMEM>>>(h_nei, e_ij, eW1, eW2, eb2);
    node_kernel<<<nsm, 256, NODE_SMEM>>>(h_self, nW1, nb1, nW2, nb2, out, tilesAC);
}